// round 15
// baseline (speedup 1.0000x reference)
#include <cuda_runtime.h>
#include <cstdint>

#define NN 768
#define NA 192
#define DD 128
#define HH 6
#define HD 768
#define MM 96
#define PSZ (HD*NN)
#define SCALE 0.08838834764831845f
#define NB 144
#define NT 512

// ---------------- device scratch ----------------
__device__ float g_p[3*PSZ];
__device__ float g_psum[3*NN*24];
__device__ float g_att[NN*HD];
__device__ float g_part[6*NN*DD];
__device__ int   g_inv[NN];
__device__ unsigned int g_count = 0;
__device__ unsigned int g_gen = 0;

__device__ __forceinline__ void gsync(unsigned int base, unsigned int i) {
    __threadfence();
    __syncthreads();
    if (threadIdx.x == 0) {
        unsigned int old = atomicInc(&g_count, NB - 1u);
        if (old == NB - 1u) {
            atomicExch(&g_gen, base + i);
        } else {
            while ((*(volatile unsigned int*)&g_gen - base) < i) { }
            __threadfence();
        }
    }
    __syncthreads();
}

__device__ __forceinline__ uint32_t f2tf(float x) {
    uint32_t r;
    asm("cvt.rna.tf32.f32 %0, %1;" : "=r"(r) : "f"(x));
    return r;
}
__device__ __forceinline__ void st4(uint32_t* ph, uint32_t* pl, float4 v) {
    uint4 h, lo;
    h.x = f2tf(v.x); lo.x = f2tf(v.x - __uint_as_float(h.x));
    h.y = f2tf(v.y); lo.y = f2tf(v.y - __uint_as_float(h.y));
    h.z = f2tf(v.z); lo.z = f2tf(v.z - __uint_as_float(h.z));
    h.w = f2tf(v.w); lo.w = f2tf(v.w - __uint_as_float(h.w));
    *(uint4*)ph = h; *(uint4*)pl = lo;
}
__device__ __forceinline__ void mma_tf32(float* d, const uint32_t* a, const uint32_t* b) {
    asm("mma.sync.aligned.m16n8k8.row.col.f32.tf32.tf32.f32 "
        "{%0,%1,%2,%3}, {%4,%5,%6,%7}, {%8,%9}, {%0,%1,%2,%3};"
        : "+f"(d[0]), "+f"(d[1]), "+f"(d[2]), "+f"(d[3])
        : "r"(a[0]), "r"(a[1]), "r"(a[2]), "r"(a[3]), "r"(b[0]), "r"(b[1]));
}

// max smem: stage2 = 47488 floats = 189952 B (stage1 = 47360)
#define DYN_SMEM (47488*4)

__global__ void __launch_bounds__(NT) megak(
    const float* __restrict__ agents, const int* __restrict__ agent_ids,
    const float* __restrict__ lanes,  const int* __restrict__ lane_ids,
    const float* __restrict__ Wq, const float* __restrict__ gq, const float* __restrict__ bq,
    const float* __restrict__ Wk, const float* __restrict__ gk, const float* __restrict__ bk,
    const float* __restrict__ Wv, const float* __restrict__ gv, const float* __restrict__ bv,
    const float* __restrict__ Wo1, const float* __restrict__ go1, const float* __restrict__ bo1,
    const float* __restrict__ Wo2, const float* __restrict__ W1,
    const float* __restrict__ gn, const float* __restrict__ bn,
    const float* __restrict__ W2, float* __restrict__ out)
{
    extern __shared__ float sm[];
    uint32_t* smU = (uint32_t*)sm;
    int tid = threadIdx.x;
    int bid = blockIdx.x;
    unsigned int base = 0;
    if (tid == 0) base = *(volatile unsigned int*)&g_gen;

    if (bid == 0) {
        for (int t = tid; t < NN; t += NT) {
            if (t < NA) g_inv[agent_ids[t]] = t;
            else        g_inv[NA + lane_ids[t - NA]] = t;
        }
    }

    // ===== stage 1: sel-fused QKV GEMM (144 jobs: 12 mt x 12 nch) ========
    {
        uint32_t* Ah = smU;                  // 64 x 68
        uint32_t* Al = smU + 4352;
        uint32_t* Wh = smU + 8704;           // 192 x 68
        uint32_t* Wl = smU + 21760;
        float*    Cs = sm + 34816;           // 64 x 196
        int mt = bid % 12, nch = bid / 12;
        int m0 = mt*64, w0 = nch*64;
        const float* Ab = m0 < NA ? agents + m0*DD : lanes + (m0 - NA)*DD;
        int w = tid >> 5, l = tid & 31;
        int mgrp = w >> 3, nb = w & 7;
        int g = l >> 2, t4 = l & 3;
        float acc[2][3][4] = {};
        for (int kc = 0; kc < 2; kc++) {
            int k0g = kc*64;
            if (kc) __syncthreads();
#pragma unroll
            for (int i = 0; i < 2; i++) {
                int lin = tid + i*NT;
                int row = lin >> 4, c4 = lin & 15;
                float4 v = *(const float4*)&Ab[row*DD + k0g + c4*4];
                st4(&Ah[row*68 + c4*4], &Al[row*68 + c4*4], v);
            }
#pragma unroll
            for (int i = 0; i < 6; i++) {
                int lin = tid + i*NT;
                int row = lin >> 4, c4 = lin & 15;
                const float* Wp = row < 64 ? Wq : (row < 128 ? Wk : Wv);
                int r = row & 63;
                float4 v = *(const float4*)&Wp[(w0+r)*DD + k0g + c4*4];
                st4(&Wh[row*68 + c4*4], &Wl[row*68 + c4*4], v);
            }
            __syncthreads();
#pragma unroll
            for (int ks = 0; ks < 8; ks++) {
                int kk = ks*8 + t4;
                uint32_t bh[3][2], bl[3][2];
#pragma unroll
                for (int j = 0; j < 3; j++) {
                    int br = (nb*24 + 8*j + g)*68 + kk;
                    bh[j][0] = Wh[br]; bh[j][1] = Wh[br+4];
                    bl[j][0] = Wl[br]; bl[j][1] = Wl[br+4];
                }
#pragma unroll
                for (int tt = 0; tt < 2; tt++) {
                    int ar = ((mgrp*2+tt)*16 + g)*68 + kk;
                    uint32_t ah[4] = {Ah[ar], Ah[ar+544], Ah[ar+4], Ah[ar+548]};
                    uint32_t al[4] = {Al[ar], Al[ar+544], Al[ar+4], Al[ar+548]};
#pragma unroll
                    for (int j = 0; j < 3; j++) {
                        mma_tf32(acc[tt][j], ah, bh[j]);
                        mma_tf32(acc[tt][j], ah, bl[j]);
                        mma_tf32(acc[tt][j], al, bh[j]);
                    }
                }
            }
        }
#pragma unroll
        for (int tt = 0; tt < 2; tt++)
#pragma unroll
            for (int j = 0; j < 3; j++) {
                int r0 = (mgrp*2+tt)*16 + g;
                int col = nb*24 + 8*j + 2*t4;
                *(float2*)&Cs[r0*196 + col]     = make_float2(acc[tt][j][0], acc[tt][j][1]);
                *(float2*)&Cs[(r0+8)*196 + col] = make_float2(acc[tt][j][2], acc[tt][j][3]);
            }
        __syncthreads();
        {
            int row = tid >> 3, q = tid & 7;
#pragma unroll
            for (int sel = 0; sel < 3; sel++) {
                float4 v0 = *(float4*)&Cs[row*196 + sel*64 + q*8];
                float4 v1 = *(float4*)&Cs[row*196 + sel*64 + q*8 + 4];
                float s  = v0.x+v0.y+v0.z+v0.w + v1.x+v1.y+v1.z+v1.w;
                float s2 = v0.x*v0.x+v0.y*v0.y+v0.z*v0.z+v0.w*v0.w
                         + v1.x*v1.x+v1.y*v1.y+v1.z*v1.z+v1.w*v1.w;
#pragma unroll
                for (int o = 4; o > 0; o >>= 1) {
                    s  += __shfl_xor_sync(0xffffffffu, s,  o);
                    s2 += __shfl_xor_sync(0xffffffffu, s2, o);
                }
                float* gp = &g_p[sel*PSZ + (m0+row)*HD + w0 + q*8];
                *(float4*)gp = v0;
                *(float4*)(gp+4) = v1;
                if (q == 0) {
                    g_psum[(sel*NN + m0+row)*24 + nch*2 + 0] = s;
                    g_psum[(sel*NN + m0+row)*24 + nch*2 + 1] = s2;
                }
            }
        }
    }
    gsync(base, 1);

    // ===== stage 2: tensor-core attention, staged V transpose ============
    {
        uint32_t* Qhi = smU;                // 32 x 132  [0, 4224)
        uint32_t* Qlo = Qhi + 4224;         // [4224, 8448)
        uint32_t* Khi = smU + 8448;         // 96 x 132 [8448, 21120)
        uint32_t* Klo = smU + 21120;        // [21120, 33792)
        // post-scores aliases (Q/K dead):
        uint32_t* Vthi = smU;               // 128 x 100 [0, 12800)
        uint32_t* Vtlo = smU + 12800;       // [12800, 25600)
        float*    Sraw = sm + 25600;        // 32 x 100 [25600, 28800)
        uint32_t* Shi  = smU + 25600;       // aliases Sraw
        uint32_t* Slo  = smU + 28800;       // [28800, 32000)
        float* Vstage = sm + 33792;         // 96 x 129 [33792, 46176)
        float* s_mu = sm + 46176;           // 224
        float* s_rs = sm + 46400;           // 224
        float* s_g  = sm + 46624;           // 384
        float* s_b  = sm + 47008;           // 384
        int*   mem  = (int*)(sm + 47392);   // 96

        int rb = bid % 3, head = (bid/3) % HH, gph = bid / (3*HH);
        if (tid < MM)
            mem[tid] = tid < 24 ? agent_ids[gph*24 + tid]
                                : NA + lane_ids[gph*72 + (tid - 24)];
        __syncthreads();
        if (tid < 224) {
            int mat, node;
            if (tid < 32)       { mat = 0; node = mem[rb*32 + tid]; }
            else if (tid < 128) { mat = 1; node = mem[tid - 32]; }
            else                { mat = 2; node = mem[tid - 128]; }
            const float* ps = &g_psum[(mat*NN + node)*24];
            float s = 0.f, s2 = 0.f;
#pragma unroll
            for (int n = 0; n < 12; n++) { s += ps[2*n]; s2 += ps[2*n+1]; }
            float mu = s * (1.f/HD);
            float var = s2 * (1.f/HD) - mu*mu;
            s_mu[tid] = mu;
            s_rs[tid] = rsqrtf(var + 1e-5f);
        }
        for (int t = tid; t < 384; t += NT) {
            int mat = t >> 7, c = t & 127;
            const float* g  = mat==0 ? gq : (mat==1 ? gk : gv);
            const float* bb = mat==0 ? bq : (mat==1 ? bk : bv);
            s_g[t] = g[head*DD + c];
            s_b[t] = bb[head*DD + c];
        }
        __syncthreads();
        // Q LN + split (pitch 132)
#pragma unroll
        for (int i = 0; i < 2; i++) {
            int lin = tid + i*NT;
            int row = lin >> 5, c4 = lin & 31;
            int node = mem[rb*32 + row];
            float4 v = *(const float4*)&g_p[node*HD + head*DD + c4*4];
            float mu = s_mu[row], rs = s_rs[row];
            float4 x;
            x.x = (v.x-mu)*rs*s_g[c4*4+0] + s_b[c4*4+0];
            x.y = (v.y-mu)*rs*s_g[c4*4+1] + s_b[c4*4+1];
            x.z = (v.z-mu)*rs*s_g[c4*4+2] + s_b[c4*4+2];
            x.w = (v.w-mu)*rs*s_g[c4*4+3] + s_b[c4*4+3];
            st4(&Qhi[row*132 + c4*4], &Qlo[row*132 + c4*4], x);
        }
        // K LN + split
#pragma unroll
        for (int i = 0; i < 6; i++) {
            int lin = tid + i*NT;
            int row = lin >> 5, c4 = lin & 31;
            int node = mem[row];
            float4 v = *(const float4*)&g_p[PSZ + node*HD + head*DD + c4*4];
            float mu = s_mu[32+row], rs = s_rs[32+row];
            float4 x;
            x.x = (v.x-mu)*rs*s_g[128+c4*4+0] + s_b[128+c4*4+0];
            x.y = (v.y-mu)*rs*s_g[128+c4*4+1] + s_b[128+c4*4+1];
            x.z = (v.z-mu)*rs*s_g[128+c4*4+2] + s_b[128+c4*4+2];
            x.w = (v.w-mu)*rs*s_g[128+c4*4+3] + s_b[128+c4*4+3];
            st4(&Khi[row*132 + c4*4], &Klo[row*132 + c4*4], x);
        }
        // V staged load: coalesced scalar, LN + relu (row const per warp)
#pragma unroll
        for (int i = 0; i < 24; i++) {
            int lin = tid + i*NT;
            int row = lin >> 7, dim = lin & 127;
            int node = mem[row];
            float x = g_p[2*PSZ + node*HD + head*DD + dim];
            x = (x - s_mu[128+row]) * s_rs[128+row] * s_g[256+dim] + s_b[256+dim];
            Vstage[row*129 + dim] = fmaxf(x, 0.f);
        }
        __syncthreads();

        int w = tid >> 5, l = tid & 31;
        int g = l >> 2, t4 = l & 3;
        // scores: S[32,96] = Q @ K^T (warps 0..11)
        float accS[2][4] = {};
        if (w < 12) {
#pragma unroll
            for (int ks = 0; ks < 16; ks++) {
                int k0 = ks*8 + t4;
                int br = (w*8 + g)*132 + k0;
                uint32_t bh[2] = {Khi[br], Khi[br+4]};
                uint32_t bl[2] = {Klo[br], Klo[br+4]};
#pragma unroll
                for (int mt = 0; mt < 2; mt++) {
                    int ar = (mt*16 + g)*132 + k0;
                    uint32_t ah[4] = {Qhi[ar], Qhi[ar+1056], Qhi[ar+4], Qhi[ar+1060]};
                    uint32_t al[4] = {Qlo[ar], Qlo[ar+1056], Qlo[ar+4], Qlo[ar+1060]};
                    mma_tf32(accS[mt], ah, bh);
                    mma_tf32(accS[mt], ah, bl);
                    mma_tf32(accS[mt], al, bh);
                }
            }
        }
        __syncthreads();   // Q/K reads complete; Vt region reusable
        // Sraw write (w<12) + V transpose (all warps, conflict-free)
        if (w < 12) {
#pragma unroll
            for (int mt = 0; mt < 2; mt++) {
                int r0 = mt*16 + g;
                int col = w*8 + 2*t4;
                *(float2*)&Sraw[r0*100 + col]     = make_float2(accS[mt][0]*SCALE, accS[mt][1]*SCALE);
                *(float2*)&Sraw[(r0+8)*100 + col] = make_float2(accS[mt][2]*SCALE, accS[mt][3]*SCALE);
            }
        }
#pragma unroll
        for (int d = 0; d < 8; d++) {
            int dim = w*8 + d;
#pragma unroll
            for (int j = 0; j < 3; j++) {
                int row = l + 32*j;
                float x = Vstage[row*129 + dim];
                uint32_t h = f2tf(x);
                Vthi[dim*100 + row] = h;
                Vtlo[dim*100 + row] = f2tf(x - __uint_as_float(h));
            }
        }
        __syncthreads();
        // softmax: warp w rows 2w,2w+1; lane covers cols l, l+32, l+64
#pragma unroll
        for (int i = 0; i < 2; i++) {
            int r = 2*w + i;
            float x0 = Sraw[r*100 + l];
            float x1 = Sraw[r*100 + l + 32];
            float x2 = Sraw[r*100 + l + 64];
            float mx = fmaxf(x0, fmaxf(x1, x2));
#pragma unroll
            for (int o = 16; o > 0; o >>= 1) mx = fmaxf(mx, __shfl_xor_sync(0xffffffffu, mx, o));
            float p0 = __expf(x0 - mx), p1 = __expf(x1 - mx), p2 = __expf(x2 - mx);
            float sum = p0 + p1 + p2;
#pragma unroll
            for (int o = 16; o > 0; o >>= 1) sum += __shfl_xor_sync(0xffffffffu, sum, o);
            float inv = 1.f / sum;
            p0 *= inv; p1 *= inv; p2 *= inv;
            uint32_t h0 = f2tf(p0), h1 = f2tf(p1), h2 = f2tf(p2);
            Shi[r*100 + l]      = h0; Slo[r*100 + l]      = f2tf(p0 - __uint_as_float(h0));
            Shi[r*100 + l + 32] = h1; Slo[r*100 + l + 32] = f2tf(p1 - __uint_as_float(h1));
            Shi[r*100 + l + 64] = h2; Slo[r*100 + l + 64] = f2tf(p2 - __uint_as_float(h2));
        }
        __syncthreads();
        // out = S @ V : M=32, N=128 (n-tile = w), K=96
        float accO[2][4] = {};
#pragma unroll
        for (int ks = 0; ks < 12; ks++) {
            int k0 = ks*8 + t4;
            int br = (w*8 + g)*100 + k0;
            uint32_t bh[2] = {Vthi[br], Vthi[br+4]};
            uint32_t bl[2] = {Vtlo[br], Vtlo[br+4]};
#pragma unroll
            for (int mt = 0; mt < 2; mt++) {
                int ar = (mt*16 + g)*100 + k0;
                uint32_t ah[4] = {Shi[ar], Shi[ar+800], Shi[ar+4], Shi[ar+804]};
                uint32_t al[4] = {Slo[ar], Slo[ar+800], Slo[ar+4], Slo[ar+804]};
                mma_tf32(accO[mt], ah, bh);
                mma_tf32(accO[mt], al, bh);
                mma_tf32(accO[mt], ah, bl);
            }
        }
#pragma unroll
        for (int mt = 0; mt < 2; mt++) {
            int r0 = mt*16 + g;
            int n0 = w*8 + 2*t4;
            int node0 = mem[rb*32 + r0];
            *(float2*)&g_att[node0*HD + head*DD + n0] = make_float2(accO[mt][0], accO[mt][1]);
            int node1 = mem[rb*32 + r0 + 8];
            *(float2*)&g_att[node1*HD + head*DD + n0] = make_float2(accO[mt][2], accO[mt][3]);
        }
    }
    gsync(base, 2);

    // ===== stage 3: o1 split-K, m16n16 warp tiles (24 mt x 6 splits) =====
    {
        uint32_t* Ah = smU;              // 32 x 68
        uint32_t* Al = smU + 2176;
        uint32_t* Wh = smU + 4352;       // 128 x 68
        uint32_t* Wl = smU + 13056;
        int sp = bid / 24, mt = bid % 24;
        int m0 = mt*32, kb = sp*128;
        int w = tid >> 5, l = tid & 31;
        int mgrp = w >> 3, nbx = w & 7;
        int g = l >> 2, t4 = l & 3;
        float acc[2][4] = {};
        for (int kc = 0; kc < 2; kc++) {
            int k0 = kb + kc*64;
            __syncthreads();
            {
                int row = tid >> 4, c4 = tid & 15;
                float4 v = *(const float4*)&g_att[(m0+row)*HD + k0 + c4*4];
                st4(&Ah[row*68 + c4*4], &Al[row*68 + c4*4], v);
            }
#pragma unroll
            for (int i = 0; i < 4; i++) {
                int lin = tid + i*NT;
                int row = lin >> 4, c4 = lin & 15;
                float4 v = *(const float4*)&Wo1[row*HD + k0 + c4*4];
                st4(&Wh[row*68 + c4*4], &Wl[row*68 + c4*4], v);
            }
            __syncthreads();
#pragma unroll
            for (int ks = 0; ks < 8; ks++) {
                int kk = ks*8 + t4;
                int ar = (mgrp*16 + g)*68 + kk;
                uint32_t ah[4] = {Ah[ar], Ah[ar+544], Ah[ar+4], Ah[ar+548]};
                uint32_t al[4] = {Al[ar], Al[ar+544], Al[ar+4], Al[ar+548]};
#pragma unroll
                for (int j = 0; j < 2; j++) {
                    int br = (nbx*16 + 8*j + g)*68 + kk;
                    uint32_t bh[2] = {Wh[br], Wh[br+4]};
                    uint32_t bl[2] = {Wl[br], Wl[br+4]};
                    mma_tf32(acc[j], ah, bh);
                    mma_tf32(acc[j], ah, bl);
                    mma_tf32(acc[j], al, bh);
                }
            }
        }
#pragma unroll
        for (int j = 0; j < 2; j++) {
            int r0 = mgrp*16 + g;
            int col = nbx*16 + 8*j + 2*t4;
            *(float2*)&g_part[sp*(NN*DD) + (m0+r0)*DD + col]   = make_float2(acc[j][0], acc[j][1]);
            *(float2*)&g_part[sp*(NN*DD) + (m0+r0+8)*DD + col] = make_float2(acc[j][2], acc[j][3]);
        }
    }
    gsync(base, 3);

    // ====== stage 4: reduce+LN -> mid GEMM+LN -> final GEMM+res+scatter ==
    if (bid < 96) {
        float* nodes_s = sm;                 // 8 x 130
        float* r1_s    = sm + 8*130;         // 8 x 130
        float* h_s     = sm + 2*8*130;       // 8 x 130
        float* Bs      = sm + 3*8*130;       // 128 x 34
        float* red     = sm + 3*8*130 + 128*34;  // 16 x 2
        int m0 = bid*8;
        int row  = tid >> 6;
        int lane = tid & 63;
        int wid  = tid >> 5;
        const float* Ab = m0 < NA ? agents + m0*DD : lanes + (m0 - NA)*DD;
        if (tid < 256) {
            int rw = tid >> 5, c4 = tid & 31;
            float4 v = *(const float4*)&Ab[rw*DD + c4*4];
            float* d = &nodes_s[rw*130 + c4*4];
            d[0]=v.x; d[1]=v.y; d[2]=v.z; d[3]=v.w;
            float4 sv = make_float4(0.f,0.f,0.f,0.f);
#pragma unroll
            for (int sp = 0; sp < 6; sp++) {
                float4 u = *(const float4*)&g_part[sp*(NN*DD) + (m0+rw)*DD + c4*4];
                sv.x += u.x; sv.y += u.y; sv.z += u.z; sv.w += u.w;
            }
            float* e = &r1_s[rw*130 + c4*4];
            e[0]=sv.x; e[1]=sv.y; e[2]=sv.z; e[3]=sv.w;
        }
        __syncthreads();
        {
            float x0 = r1_s[row*130 + lane];
            float x1 = r1_s[row*130 + lane + 64];
            float s = x0 + x1, s2 = x0*x0 + x1*x1;
#pragma unroll
            for (int o = 16; o > 0; o >>= 1) {
                s  += __shfl_xor_sync(0xffffffffu, s,  o);
                s2 += __shfl_xor_sync(0xffffffffu, s2, o);
            }
            if ((tid & 31) == 0) { red[wid*2] = s; red[wid*2+1] = s2; }
            __syncthreads();
            float ss  = red[(wid^1)*2]   + red[wid*2];
            float ss2 = red[(wid^1)*2+1] + red[wid*2+1];
            float mu = ss*(1.f/DD), var = ss2*(1.f/DD) - mu*mu;
            float rstd = rsqrtf(var + 1e-5f);
            r1_s[row*130 + lane]      = fmaxf((x0-mu)*rstd*go1[lane]    + bo1[lane],    0.f);
            r1_s[row*130 + lane + 64] = fmaxf((x1-mu)*rstd*go1[lane+64] + bo1[lane+64], 0.f);
        }
        __syncthreads();
        float acc[2] = {};
        float4 wreg[2];
        {
            int lin0 = tid, lin1 = tid + NT;
            wreg[0] = *(const float4*)&W1[(lin0>>3)*DD + (lin0&7)*4];
            wreg[1] = *(const float4*)&W1[(lin1>>3)*DD + (lin1&7)*4];
        }
        for (int cc = 0; cc < 8; cc++) {
#pragma unroll
            for (int i = 0; i < 2; i++) {
                int lin = tid + i*NT;
                int rw = lin >> 3, c4 = lin & 7;
                float* d = &Bs[rw*34 + c4*4];
                d[0]=wreg[i].x; d[1]=wreg[i].y; d[2]=wreg[i].z; d[3]=wreg[i].w;
            }
            if (cc < 7) {
                const float* Wn = (cc+1) < 4 ? W1 : Wo2;
                int k0n = ((cc+1) & 3) * 32;
#pragma unroll
                for (int i = 0; i < 2; i++) {
                    int lin = tid + i*NT;
                    wreg[i] = *(const float4*)&Wn[(lin>>3)*DD + k0n + (lin&7)*4];
                }
            }
            const float* A = cc < 4 ? nodes_s : r1_s;
            int k0 = (cc & 3) * 32;
            __syncthreads();
#pragma unroll 4
            for (int k2 = 0; k2 < 32; k2 += 2) {
                float2 a = *(float2*)&A[row*130 + k0 + k2];
#pragma unroll
                for (int j = 0; j < 2; j++) {
                    float2 b = *(float2*)&Bs[(lane + 64*j)*34 + k2];
                    acc[j] += a.x*b.x; acc[j] += a.y*b.y;
                }
            }
            __syncthreads();
        }
        {
            float s = acc[0] + acc[1], s2 = acc[0]*acc[0] + acc[1]*acc[1];
#pragma unroll
            for (int o = 16; o > 0; o >>= 1) {
                s  += __shfl_xor_sync(0xffffffffu, s,  o);
                s2 += __shfl_xor_sync(0xffffffffu, s2, o);
            }
            if ((tid & 31) == 0) { red[wid*2] = s; red[wid*2+1] = s2; }
            __syncthreads();
            float ss  = red[(wid^1)*2]   + red[wid*2];
            float ss2 = red[(wid^1)*2+1] + red[wid*2+1];
            float mu = ss*(1.f/DD), var = ss2*(1.f/DD) - mu*mu;
            float rstd = rsqrtf(var + 1e-5f);
            h_s[row*130 + lane]      = fmaxf((acc[0]-mu)*rstd*gn[lane]    + bn[lane],    0.f);
            h_s[row*130 + lane + 64] = fmaxf((acc[1]-mu)*rstd*gn[lane+64] + bn[lane+64], 0.f);
        }
        __syncthreads();
        float acc2[2] = {};
        {
            int lin0 = tid, lin1 = tid + NT;
            wreg[0] = *(const float4*)&W2[(lin0>>3)*DD + (lin0&7)*4];
            wreg[1] = *(const float4*)&W2[(lin1>>3)*DD + (lin1&7)*4];
        }
        for (int cc = 0; cc < 4; cc++) {
#pragma unroll
            for (int i = 0; i < 2; i++) {
                int lin = tid + i*NT;
                int rw = lin >> 3, c4 = lin & 7;
                float* d = &Bs[rw*34 + c4*4];
                d[0]=wreg[i].x; d[1]=wreg[i].y; d[2]=wreg[i].z; d[3]=wreg[i].w;
            }
            if (cc < 3) {
                int k0n = (cc+1) * 32;
#pragma unroll
                for (int i = 0; i < 2; i++) {
                    int lin = tid + i*NT;
                    wreg[i] = *(const float4*)&W2[(lin>>3)*DD + k0n + (lin&7)*4];
                }
            }
            int k0 = cc * 32;
            __syncthreads();
#pragma unroll 4
            for (int k2 = 0; k2 < 32; k2 += 2) {
                float2 a = *(float2*)&h_s[row*130 + k0 + k2];
#pragma unroll
                for (int j = 0; j < 2; j++) {
                    float2 b = *(float2*)&Bs[(lane + 64*j)*34 + k2];
                    acc2[j] += a.x*b.x; acc2[j] += a.y*b.y;
                }
            }
            __syncthreads();
        }
        int orow = g_inv[m0 + row];
#pragma unroll
        for (int j = 0; j < 2; j++) {
            int c = lane + 64*j;
            out[orow*DD + c] = fmaxf(acc2[j] + nodes_s[row*130 + c], 0.f);
        }
    }
}

// ------------------------------------------------------------------------
extern "C" void kernel_launch(void* const* d_in, const int* in_sizes, int n_in,
                              void* d_out, int out_size) {
    const float* agents    = (const float*)d_in[0];
    const int*   agent_ids = (const int*)  d_in[1];
    const float* lanes     = (const float*)d_in[2];
    const int*   lane_ids  = (const int*)  d_in[3];
    const float* Wq  = (const float*)d_in[4];
    const float* gq  = (const float*)d_in[5];
    const float* bq  = (const float*)d_in[6];
    const float* Wk  = (const float*)d_in[7];
    const float* gk  = (const float*)d_in[8];
    const float* bk  = (const float*)d_in[9];
    const float* Wv  = (const float*)d_in[10];
    const float* gv  = (const float*)d_in[11];
    const float* bv  = (const float*)d_in[12];
    const float* Wo1 = (const float*)d_in[13];
    const float* go1 = (const float*)d_in[14];
    const float* bo1 = (const float*)d_in[15];
    const float* Wo2 = (const float*)d_in[16];
    const float* W1  = (const float*)d_in[17];
    const float* gn  = (const float*)d_in[18];
    const float* bn  = (const float*)d_in[19];
    const float* W2  = (const float*)d_in[20];
    float* out = (float*)d_out;

    cudaFuncSetAttribute(megak, cudaFuncAttributeMaxDynamicSharedMemorySize, DYN_SMEM);

    megak<<<NB, NT, DYN_SMEM>>>(agents, agent_ids, lanes, lane_ids,
                                Wq, gq, bq, Wk, gk, bk, Wv, gv, bv,
                                Wo1, go1, bo1, Wo2, W1, gn, bn, W2, out);
}

// round 16
// speedup vs baseline: 1.0757x; 1.0757x over previous
#include <cuda_runtime.h>
#include <cstdint>

#define NN 768
#define NA 192
#define DD 128
#define HH 6
#define HD 768
#define MM 96
#define PSZ (HD*NN)
#define SCALE 0.08838834764831845f
#define NB 144
#define NT 512

// ---------------- device scratch ----------------
__device__ float g_p[3*PSZ];
__device__ float g_psum[3*NN*24];
__device__ float g_att[NN*HD];
__device__ float g_part[6*NN*DD];
__device__ int   g_inv[NN];
__device__ unsigned int g_count = 0;
__device__ unsigned int g_gen = 0;

__device__ __forceinline__ void gsync(unsigned int base, unsigned int i) {
    __threadfence();
    __syncthreads();
    if (threadIdx.x == 0) {
        unsigned int old = atomicInc(&g_count, NB - 1u);
        if (old == NB - 1u) {
            atomicExch(&g_gen, base + i);
        } else {
            while ((*(volatile unsigned int*)&g_gen - base) < i) { }
            __threadfence();
        }
    }
    __syncthreads();
}

__device__ __forceinline__ uint32_t f2tf(float x) {
    uint32_t r;
    asm("cvt.rna.tf32.f32 %0, %1;" : "=r"(r) : "f"(x));
    return r;
}
__device__ __forceinline__ void st4(uint32_t* ph, uint32_t* pl, float4 v) {
    uint4 h, lo;
    h.x = f2tf(v.x); lo.x = f2tf(v.x - __uint_as_float(h.x));
    h.y = f2tf(v.y); lo.y = f2tf(v.y - __uint_as_float(h.y));
    h.z = f2tf(v.z); lo.z = f2tf(v.z - __uint_as_float(h.z));
    h.w = f2tf(v.w); lo.w = f2tf(v.w - __uint_as_float(h.w));
    *(uint4*)ph = h; *(uint4*)pl = lo;
}
__device__ __forceinline__ void st4h(uint32_t* ph, float4 v) {
    uint4 h;
    h.x = f2tf(v.x); h.y = f2tf(v.y); h.z = f2tf(v.z); h.w = f2tf(v.w);
    *(uint4*)ph = h;
}
__device__ __forceinline__ void mma_tf32(float* d, const uint32_t* a, const uint32_t* b) {
    asm("mma.sync.aligned.m16n8k8.row.col.f32.tf32.tf32.f32 "
        "{%0,%1,%2,%3}, {%4,%5,%6,%7}, {%8,%9}, {%0,%1,%2,%3};"
        : "+f"(d[0]), "+f"(d[1]), "+f"(d[2]), "+f"(d[3])
        : "r"(a[0]), "r"(a[1]), "r"(a[2]), "r"(a[3]), "r"(b[0]), "r"(b[1]));
}

// max smem: stage2 = 47488 floats = 189952 B
#define DYN_SMEM (47488*4)

__global__ void __launch_bounds__(NT) megak(
    const float* __restrict__ agents, const int* __restrict__ agent_ids,
    const float* __restrict__ lanes,  const int* __restrict__ lane_ids,
    const float* __restrict__ Wq, const float* __restrict__ gq, const float* __restrict__ bq,
    const float* __restrict__ Wk, const float* __restrict__ gk, const float* __restrict__ bk,
    const float* __restrict__ Wv, const float* __restrict__ gv, const float* __restrict__ bv,
    const float* __restrict__ Wo1, const float* __restrict__ go1, const float* __restrict__ bo1,
    const float* __restrict__ Wo2, const float* __restrict__ W1,
    const float* __restrict__ gn, const float* __restrict__ bn,
    const float* __restrict__ W2, float* __restrict__ out)
{
    extern __shared__ float sm[];
    uint32_t* smU = (uint32_t*)sm;
    int tid = threadIdx.x;
    int bid = blockIdx.x;
    unsigned int base = 0;
    if (tid == 0) base = *(volatile unsigned int*)&g_gen;

    if (bid == 0) {
        for (int t = tid; t < NN; t += NT) {
            if (t < NA) g_inv[agent_ids[t]] = t;
            else        g_inv[NA + lane_ids[t - NA]] = t;
        }
    }

    // ===== stage 1: sel-fused QKV GEMM, A 2-term x W hi-only =============
    {
        uint32_t* Ah = smU;                  // 64 x 68
        uint32_t* Al = smU + 4352;
        uint32_t* Wh = smU + 8704;           // 192 x 68
        float*    Cs = sm + 21760;           // 64 x 196
        int mt = bid % 12, nch = bid / 12;
        int m0 = mt*64, w0 = nch*64;
        const float* Ab = m0 < NA ? agents + m0*DD : lanes + (m0 - NA)*DD;
        int w = tid >> 5, l = tid & 31;
        int mgrp = w >> 3, nb = w & 7;
        int g = l >> 2, t4 = l & 3;
        float acc[2][3][4] = {};
        for (int kc = 0; kc < 2; kc++) {
            int k0g = kc*64;
            if (kc) __syncthreads();
#pragma unroll
            for (int i = 0; i < 2; i++) {
                int lin = tid + i*NT;
                int row = lin >> 4, c4 = lin & 15;
                float4 v = *(const float4*)&Ab[row*DD + k0g + c4*4];
                st4(&Ah[row*68 + c4*4], &Al[row*68 + c4*4], v);
            }
#pragma unroll
            for (int i = 0; i < 6; i++) {
                int lin = tid + i*NT;
                int row = lin >> 4, c4 = lin & 15;
                const float* Wp = row < 64 ? Wq : (row < 128 ? Wk : Wv);
                int r = row & 63;
                float4 v = *(const float4*)&Wp[(w0+r)*DD + k0g + c4*4];
                st4h(&Wh[row*68 + c4*4], v);
            }
            __syncthreads();
#pragma unroll
            for (int ks = 0; ks < 8; ks++) {
                int kk = ks*8 + t4;
                uint32_t bh[3][2];
#pragma unroll
                for (int j = 0; j < 3; j++) {
                    int br = (nb*24 + 8*j + g)*68 + kk;
                    bh[j][0] = Wh[br]; bh[j][1] = Wh[br+4];
                }
#pragma unroll
                for (int tt = 0; tt < 2; tt++) {
                    int ar = ((mgrp*2+tt)*16 + g)*68 + kk;
                    uint32_t ah[4] = {Ah[ar], Ah[ar+544], Ah[ar+4], Ah[ar+548]};
                    uint32_t al[4] = {Al[ar], Al[ar+544], Al[ar+4], Al[ar+548]};
#pragma unroll
                    for (int j = 0; j < 3; j++) {
                        mma_tf32(acc[tt][j], ah, bh[j]);
                        mma_tf32(acc[tt][j], al, bh[j]);
                    }
                }
            }
        }
#pragma unroll
        for (int tt = 0; tt < 2; tt++)
#pragma unroll
            for (int j = 0; j < 3; j++) {
                int r0 = (mgrp*2+tt)*16 + g;
                int col = nb*24 + 8*j + 2*t4;
                *(float2*)&Cs[r0*196 + col]     = make_float2(acc[tt][j][0], acc[tt][j][1]);
                *(float2*)&Cs[(r0+8)*196 + col] = make_float2(acc[tt][j][2], acc[tt][j][3]);
            }
        __syncthreads();
        {
            int row = tid >> 3, q = tid & 7;
#pragma unroll
            for (int sel = 0; sel < 3; sel++) {
                float4 v0 = *(float4*)&Cs[row*196 + sel*64 + q*8];
                float4 v1 = *(float4*)&Cs[row*196 + sel*64 + q*8 + 4];
                float s  = v0.x+v0.y+v0.z+v0.w + v1.x+v1.y+v1.z+v1.w;
                float s2 = v0.x*v0.x+v0.y*v0.y+v0.z*v0.z+v0.w*v0.w
                         + v1.x*v1.x+v1.y*v1.y+v1.z*v1.z+v1.w*v1.w;
#pragma unroll
                for (int o = 4; o > 0; o >>= 1) {
                    s  += __shfl_xor_sync(0xffffffffu, s,  o);
                    s2 += __shfl_xor_sync(0xffffffffu, s2, o);
                }
                float* gp = &g_p[sel*PSZ + (m0+row)*HD + w0 + q*8];
                *(float4*)gp = v0;
                *(float4*)(gp+4) = v1;
                if (q == 0) {
                    g_psum[(sel*NN + m0+row)*24 + nch*2 + 0] = s;
                    g_psum[(sel*NN + m0+row)*24 + nch*2 + 1] = s2;
                }
            }
        }
    }
    gsync(base, 1);

    // ===== stage 2: tensor-core attention (scores 3-term, AV V-hi) =======
    {
        uint32_t* Qhi = smU;                // 32 x 132  [0, 4224)
        uint32_t* Qlo = Qhi + 4224;         // [4224, 8448)
        uint32_t* Khi = smU + 8448;         // 96 x 132 [8448, 21120)
        uint32_t* Klo = smU + 21120;        // [21120, 33792)
        // post-scores aliases (Q/K dead):
        uint32_t* Vthi = smU;               // 128 x 100 [0, 12800)
        float*    Sraw = sm + 12800;        // 32 x 100 [12800, 16000)
        uint32_t* Shi  = smU + 12800;       // aliases Sraw
        uint32_t* Slo  = smU + 16000;       // [16000, 19200)
        float* Vstage = sm + 33792;         // 96 x 129 [33792, 46176)
        float* s_mu = sm + 46176;
        float* s_rs = sm + 46400;
        float* s_g  = sm + 46624;
        float* s_b  = sm + 47008;
        int*   mem  = (int*)(sm + 47392);

        int rb = bid % 3, head = (bid/3) % HH, gph = bid / (3*HH);
        if (tid < MM)
            mem[tid] = tid < 24 ? agent_ids[gph*24 + tid]
                                : NA + lane_ids[gph*72 + (tid - 24)];
        __syncthreads();
        if (tid < 224) {
            int mat, node;
            if (tid < 32)       { mat = 0; node = mem[rb*32 + tid]; }
            else if (tid < 128) { mat = 1; node = mem[tid - 32]; }
            else                { mat = 2; node = mem[tid - 128]; }
            const float* ps = &g_psum[(mat*NN + node)*24];
            float s = 0.f, s2 = 0.f;
#pragma unroll
            for (int n = 0; n < 12; n++) { s += ps[2*n]; s2 += ps[2*n+1]; }
            float mu = s * (1.f/HD);
            float var = s2 * (1.f/HD) - mu*mu;
            s_mu[tid] = mu;
            s_rs[tid] = rsqrtf(var + 1e-5f);
        }
        for (int t = tid; t < 384; t += NT) {
            int mat = t >> 7, c = t & 127;
            const float* g  = mat==0 ? gq : (mat==1 ? gk : gv);
            const float* bb = mat==0 ? bq : (mat==1 ? bk : bv);
            s_g[t] = g[head*DD + c];
            s_b[t] = bb[head*DD + c];
        }
        __syncthreads();
        // Q LN + split (pitch 132)
#pragma unroll
        for (int i = 0; i < 2; i++) {
            int lin = tid + i*NT;
            int row = lin >> 5, c4 = lin & 31;
            int node = mem[rb*32 + row];
            float4 v = *(const float4*)&g_p[node*HD + head*DD + c4*4];
            float mu = s_mu[row], rs = s_rs[row];
            float4 x;
            x.x = (v.x-mu)*rs*s_g[c4*4+0] + s_b[c4*4+0];
            x.y = (v.y-mu)*rs*s_g[c4*4+1] + s_b[c4*4+1];
            x.z = (v.z-mu)*rs*s_g[c4*4+2] + s_b[c4*4+2];
            x.w = (v.w-mu)*rs*s_g[c4*4+3] + s_b[c4*4+3];
            st4(&Qhi[row*132 + c4*4], &Qlo[row*132 + c4*4], x);
        }
        // K LN + split
#pragma unroll
        for (int i = 0; i < 6; i++) {
            int lin = tid + i*NT;
            int row = lin >> 5, c4 = lin & 31;
            int node = mem[row];
            float4 v = *(const float4*)&g_p[PSZ + node*HD + head*DD + c4*4];
            float mu = s_mu[32+row], rs = s_rs[32+row];
            float4 x;
            x.x = (v.x-mu)*rs*s_g[128+c4*4+0] + s_b[128+c4*4+0];
            x.y = (v.y-mu)*rs*s_g[128+c4*4+1] + s_b[128+c4*4+1];
            x.z = (v.z-mu)*rs*s_g[128+c4*4+2] + s_b[128+c4*4+2];
            x.w = (v.w-mu)*rs*s_g[128+c4*4+3] + s_b[128+c4*4+3];
            st4(&Khi[row*132 + c4*4], &Klo[row*132 + c4*4], x);
        }
        // V staged load: coalesced scalar, LN + relu
#pragma unroll
        for (int i = 0; i < 24; i++) {
            int lin = tid + i*NT;
            int row = lin >> 7, dim = lin & 127;
            int node = mem[row];
            float x = g_p[2*PSZ + node*HD + head*DD + dim];
            x = (x - s_mu[128+row]) * s_rs[128+row] * s_g[256+dim] + s_b[256+dim];
            Vstage[row*129 + dim] = fmaxf(x, 0.f);
        }
        __syncthreads();

        int w = tid >> 5, l = tid & 31;
        int g = l >> 2, t4 = l & 3;
        // scores: S[32,96] = Q @ K^T (warps 0..11), full 3-term
        float accS[2][4] = {};
        if (w < 12) {
#pragma unroll
            for (int ks = 0; ks < 16; ks++) {
                int k0 = ks*8 + t4;
                int br = (w*8 + g)*132 + k0;
                uint32_t bh[2] = {Khi[br], Khi[br+4]};
                uint32_t bl[2] = {Klo[br], Klo[br+4]};
#pragma unroll
                for (int mt = 0; mt < 2; mt++) {
                    int ar = (mt*16 + g)*132 + k0;
                    uint32_t ah[4] = {Qhi[ar], Qhi[ar+1056], Qhi[ar+4], Qhi[ar+1060]};
                    uint32_t al[4] = {Qlo[ar], Qlo[ar+1056], Qlo[ar+4], Qlo[ar+1060]};
                    mma_tf32(accS[mt], ah, bh);
                    mma_tf32(accS[mt], ah, bl);
                    mma_tf32(accS[mt], al, bh);
                }
            }
        }
        __syncthreads();   // Q/K reads complete
        if (w < 12) {
#pragma unroll
            for (int mt = 0; mt < 2; mt++) {
                int r0 = mt*16 + g;
                int col = w*8 + 2*t4;
                *(float2*)&Sraw[r0*100 + col]     = make_float2(accS[mt][0]*SCALE, accS[mt][1]*SCALE);
                *(float2*)&Sraw[(r0+8)*100 + col] = make_float2(accS[mt][2]*SCALE, accS[mt][3]*SCALE);
            }
        }
        // V transpose: hi only, conflict-free both sides
#pragma unroll
        for (int d = 0; d < 8; d++) {
            int dim = w*8 + d;
#pragma unroll
            for (int j = 0; j < 3; j++) {
                int row = l + 32*j;
                Vthi[dim*100 + row] = f2tf(Vstage[row*129 + dim]);
            }
        }
        __syncthreads();
        // softmax: warp w rows 2w,2w+1; lane covers cols l, l+32, l+64
#pragma unroll
        for (int i = 0; i < 2; i++) {
            int r = 2*w + i;
            float x0 = Sraw[r*100 + l];
            float x1 = Sraw[r*100 + l + 32];
            float x2 = Sraw[r*100 + l + 64];
            float mx = fmaxf(x0, fmaxf(x1, x2));
#pragma unroll
            for (int o = 16; o > 0; o >>= 1) mx = fmaxf(mx, __shfl_xor_sync(0xffffffffu, mx, o));
            float p0 = __expf(x0 - mx), p1 = __expf(x1 - mx), p2 = __expf(x2 - mx);
            float sum = p0 + p1 + p2;
#pragma unroll
            for (int o = 16; o > 0; o >>= 1) sum += __shfl_xor_sync(0xffffffffu, sum, o);
            float inv = 1.f / sum;
            p0 *= inv; p1 *= inv; p2 *= inv;
            uint32_t h0 = f2tf(p0), h1 = f2tf(p1), h2 = f2tf(p2);
            Shi[r*100 + l]      = h0; Slo[r*100 + l]      = f2tf(p0 - __uint_as_float(h0));
            Shi[r*100 + l + 32] = h1; Slo[r*100 + l + 32] = f2tf(p1 - __uint_as_float(h1));
            Shi[r*100 + l + 64] = h2; Slo[r*100 + l + 64] = f2tf(p2 - __uint_as_float(h2));
        }
        __syncthreads();
        // out = S @ V : S 2-term x V hi-only
        float accO[2][4] = {};
#pragma unroll
        for (int ks = 0; ks < 12; ks++) {
            int k0 = ks*8 + t4;
            int br = (w*8 + g)*100 + k0;
            uint32_t bh[2] = {Vthi[br], Vthi[br+4]};
#pragma unroll
            for (int mt = 0; mt < 2; mt++) {
                int ar = (mt*16 + g)*100 + k0;
                uint32_t ah[4] = {Shi[ar], Shi[ar+800], Shi[ar+4], Shi[ar+804]};
                uint32_t al[4] = {Slo[ar], Slo[ar+800], Slo[ar+4], Slo[ar+804]};
                mma_tf32(accO[mt], ah, bh);
                mma_tf32(accO[mt], al, bh);
            }
        }
#pragma unroll
        for (int mt = 0; mt < 2; mt++) {
            int r0 = mt*16 + g;
            int n0 = w*8 + 2*t4;
            int node0 = mem[rb*32 + r0];
            *(float2*)&g_att[node0*HD + head*DD + n0] = make_float2(accO[mt][0], accO[mt][1]);
            int node1 = mem[rb*32 + r0 + 8];
            *(float2*)&g_att[node1*HD + head*DD + n0] = make_float2(accO[mt][2], accO[mt][3]);
        }
    }
    gsync(base, 2);

    // ===== stage 3: o1 split-K, A 2-term x W hi-only =====================
    {
        uint32_t* Ah = smU;              // 32 x 68
        uint32_t* Al = smU + 2176;
        uint32_t* Wh = smU + 4352;       // 128 x 68
        int sp = bid / 24, mt = bid % 24;
        int m0 = mt*32, kb = sp*128;
        int w = tid >> 5, l = tid & 31;
        int mgrp = w >> 3, nbx = w & 7;
        int g = l >> 2, t4 = l & 3;
        float acc[2][4] = {};
        for (int kc = 0; kc < 2; kc++) {
            int k0 = kb + kc*64;
            __syncthreads();
            {
                int row = tid >> 4, c4 = tid & 15;
                float4 v = *(const float4*)&g_att[(m0+row)*HD + k0 + c4*4];
                st4(&Ah[row*68 + c4*4], &Al[row*68 + c4*4], v);
            }
#pragma unroll
            for (int i = 0; i < 4; i++) {
                int lin = tid + i*NT;
                int row = lin >> 4, c4 = lin & 15;
                float4 v = *(const float4*)&Wo1[row*HD + k0 + c4*4];
                st4h(&Wh[row*68 + c4*4], v);
            }
            __syncthreads();
#pragma unroll
            for (int ks = 0; ks < 8; ks++) {
                int kk = ks*8 + t4;
                int ar = (mgrp*16 + g)*68 + kk;
                uint32_t ah[4] = {Ah[ar], Ah[ar+544], Ah[ar+4], Ah[ar+548]};
                uint32_t al[4] = {Al[ar], Al[ar+544], Al[ar+4], Al[ar+548]};
#pragma unroll
                for (int j = 0; j < 2; j++) {
                    int br = (nbx*16 + 8*j + g)*68 + kk;
                    uint32_t bh[2] = {Wh[br], Wh[br+4]};
                    mma_tf32(acc[j], ah, bh);
                    mma_tf32(acc[j], al, bh);
                }
            }
        }
#pragma unroll
        for (int j = 0; j < 2; j++) {
            int r0 = mgrp*16 + g;
            int col = nbx*16 + 8*j + 2*t4;
            *(float2*)&g_part[sp*(NN*DD) + (m0+r0)*DD + col]   = make_float2(acc[j][0], acc[j][1]);
            *(float2*)&g_part[sp*(NN*DD) + (m0+r0+8)*DD + col] = make_float2(acc[j][2], acc[j][3]);
        }
    }
    gsync(base, 3);

    // ====== stage 4: reduce+LN -> mid GEMM+LN -> final GEMM+res+scatter ==
    if (bid < 96) {
        float* nodes_s = sm;                 // 8 x 130
        float* r1_s    = sm + 8*130;         // 8 x 130
        float* h_s     = sm + 2*8*130;       // 8 x 130
        float* Bs      = sm + 3*8*130;       // 128 x 34
        float* red     = sm + 3*8*130 + 128*34;  // 16 x 2
        int m0 = bid*8;
        int row  = tid >> 6;
        int lane = tid & 63;
        int wid  = tid >> 5;
        const float* Ab = m0 < NA ? agents + m0*DD : lanes + (m0 - NA)*DD;
        if (tid < 256) {
            int rw = tid >> 5, c4 = tid & 31;
            float4 v = *(const float4*)&Ab[rw*DD + c4*4];
            float* d = &nodes_s[rw*130 + c4*4];
            d[0]=v.x; d[1]=v.y; d[2]=v.z; d[3]=v.w;
            float4 sv = make_float4(0.f,0.f,0.f,0.f);
#pragma unroll
            for (int sp = 0; sp < 6; sp++) {
                float4 u = *(const float4*)&g_part[sp*(NN*DD) + (m0+rw)*DD + c4*4];
                sv.x += u.x; sv.y += u.y; sv.z += u.z; sv.w += u.w;
            }
            float* e = &r1_s[rw*130 + c4*4];
            e[0]=sv.x; e[1]=sv.y; e[2]=sv.z; e[3]=sv.w;
        }
        __syncthreads();
        {
            float x0 = r1_s[row*130 + lane];
            float x1 = r1_s[row*130 + lane + 64];
            float s = x0 + x1, s2 = x0*x0 + x1*x1;
#pragma unroll
            for (int o = 16; o > 0; o >>= 1) {
                s  += __shfl_xor_sync(0xffffffffu, s,  o);
                s2 += __shfl_xor_sync(0xffffffffu, s2, o);
            }
            if ((tid & 31) == 0) { red[wid*2] = s; red[wid*2+1] = s2; }
            __syncthreads();
            float ss  = red[(wid^1)*2]   + red[wid*2];
            float ss2 = red[(wid^1)*2+1] + red[wid*2+1];
            float mu = ss*(1.f/DD), var = ss2*(1.f/DD) - mu*mu;
            float rstd = rsqrtf(var + 1e-5f);
            r1_s[row*130 + lane]      = fmaxf((x0-mu)*rstd*go1[lane]    + bo1[lane],    0.f);
            r1_s[row*130 + lane + 64] = fmaxf((x1-mu)*rstd*go1[lane+64] + bo1[lane+64], 0.f);
        }
        __syncthreads();
        float acc[2] = {};
        float4 wreg[2];
        {
            int lin0 = tid, lin1 = tid + NT;
            wreg[0] = *(const float4*)&W1[(lin0>>3)*DD + (lin0&7)*4];
            wreg[1] = *(const float4*)&W1[(lin1>>3)*DD + (lin1&7)*4];
        }
        for (int cc = 0; cc < 8; cc++) {
#pragma unroll
            for (int i = 0; i < 2; i++) {
                int lin = tid + i*NT;
                int rw = lin >> 3, c4 = lin & 7;
                float* d = &Bs[rw*34 + c4*4];
                d[0]=wreg[i].x; d[1]=wreg[i].y; d[2]=wreg[i].z; d[3]=wreg[i].w;
            }
            if (cc < 7) {
                const float* Wn = (cc+1) < 4 ? W1 : Wo2;
                int k0n = ((cc+1) & 3) * 32;
#pragma unroll
                for (int i = 0; i < 2; i++) {
                    int lin = tid + i*NT;
                    wreg[i] = *(const float4*)&Wn[(lin>>3)*DD + k0n + (lin&7)*4];
                }
            }
            const float* A = cc < 4 ? nodes_s : r1_s;
            int k0 = (cc & 3) * 32;
            __syncthreads();
#pragma unroll 4
            for (int k2 = 0; k2 < 32; k2 += 2) {
                float2 a = *(float2*)&A[row*130 + k0 + k2];
#pragma unroll
                for (int j = 0; j < 2; j++) {
                    float2 b = *(float2*)&Bs[(lane + 64*j)*34 + k2];
                    acc[j] += a.x*b.x; acc[j] += a.y*b.y;
                }
            }
            __syncthreads();
        }
        {
            float s = acc[0] + acc[1], s2 = acc[0]*acc[0] + acc[1]*acc[1];
#pragma unroll
            for (int o = 16; o > 0; o >>= 1) {
                s  += __shfl_xor_sync(0xffffffffu, s,  o);
                s2 += __shfl_xor_sync(0xffffffffu, s2, o);
            }
            if ((tid & 31) == 0) { red[wid*2] = s; red[wid*2+1] = s2; }
            __syncthreads();
            float ss  = red[(wid^1)*2]   + red[wid*2];
            float ss2 = red[(wid^1)*2+1] + red[wid*2+1];
            float mu = ss*(1.f/DD), var = ss2*(1.f/DD) - mu*mu;
            float rstd = rsqrtf(var + 1e-5f);
            h_s[row*130 + lane]      = fmaxf((acc[0]-mu)*rstd*gn[lane]    + bn[lane],    0.f);
            h_s[row*130 + lane + 64] = fmaxf((acc[1]-mu)*rstd*gn[lane+64] + bn[lane+64], 0.f);
        }
        __syncthreads();
        float acc2[2] = {};
        {
            int lin0 = tid, lin1 = tid + NT;
            wreg[0] = *(const float4*)&W2[(lin0>>3)*DD + (lin0&7)*4];
            wreg[1] = *(const float4*)&W2[(lin1>>3)*DD + (lin1&7)*4];
        }
        for (int cc = 0; cc < 4; cc++) {
#pragma unroll
            for (int i = 0; i < 2; i++) {
                int lin = tid + i*NT;
                int rw = lin >> 3, c4 = lin & 7;
                float* d = &Bs[rw*34 + c4*4];
                d[0]=wreg[i].x; d[1]=wreg[i].y; d[2]=wreg[i].z; d[3]=wreg[i].w;
            }
            if (cc < 3) {
                int k0n = (cc+1) * 32;
#pragma unroll
                for (int i = 0; i < 2; i++) {
                    int lin = tid + i*NT;
                    wreg[i] = *(const float4*)&W2[(lin>>3)*DD + k0n + (lin&7)*4];
                }
            }
            int k0 = cc * 32;
            __syncthreads();
#pragma unroll 4
            for (int k2 = 0; k2 < 32; k2 += 2) {
                float2 a = *(float2*)&h_s[row*130 + k0 + k2];
#pragma unroll
                for (int j = 0; j < 2; j++) {
                    float2 b = *(float2*)&Bs[(lane + 64*j)*34 + k2];
                    acc2[j] += a.x*b.x; acc2[j] += a.y*b.y;
                }
            }
            __syncthreads();
        }
        int orow = g_inv[m0 + row];
#pragma unroll
        for (int j = 0; j < 2; j++) {
            int c = lane + 64*j;
            out[orow*DD + c] = fmaxf(acc2[j] + nodes_s[row*130 + c], 0.f);
        }
    }
}

// ------------------------------------------------------------------------
extern "C" void kernel_launch(void* const* d_in, const int* in_sizes, int n_in,
                              void* d_out, int out_size) {
    const float* agents    = (const float*)d_in[0];
    const int*   agent_ids = (const int*)  d_in[1];
    const float* lanes     = (const float*)d_in[2];
    const int*   lane_ids  = (const int*)  d_in[3];
    const float* Wq  = (const float*)d_in[4];
    const float* gq  = (const float*)d_in[5];
    const float* bq  = (const float*)d_in[6];
    const float* Wk  = (const float*)d_in[7];
    const float* gk  = (const float*)d_in[8];
    const float* bk  = (const float*)d_in[9];
    const float* Wv  = (const float*)d_in[10];
    const float* gv  = (const float*)d_in[11];
    const float* bv  = (const float*)d_in[12];
    const float* Wo1 = (const float*)d_in[13];
    const float* go1 = (const float*)d_in[14];
    const float* bo1 = (const float*)d_in[15];
    const float* Wo2 = (const float*)d_in[16];
    const float* W1  = (const float*)d_in[17];
    const float* gn  = (const float*)d_in[18];
    const float* bn  = (const float*)d_in[19];
    const float* W2  = (const float*)d_in[20];
    float* out = (float*)d_out;

    cudaFuncSetAttribute(megak, cudaFuncAttributeMaxDynamicSharedMemorySize, DYN_SMEM);

    megak<<<NB, NT, DYN_SMEM>>>(agents, agent_ids, lanes, lane_ids,
                                Wq, gq, bq, Wk, gk, bk, Wv, gv, bv,
                                Wo1, go1, bo1, Wo2, W1, gn, bn, W2, out);
}